// round 6
// baseline (speedup 1.0000x reference)
#include <cuda_runtime.h>
#include <cuda_bf16.h>
#include <cuda_fp16.h>
#include <cstdint>

// ===================== Problem constants =====================
#define TOKENS   8192
#define IN_F     2048
#define OUT_F    8192
#define BM 128
#define BN 256
#define BK 64                  // fp16 elems per K-chunk (128 bytes per row)
#define NCHUNK (IN_F / BK)     // 32
#define STAGES 4
#define STG_SZ 49152           // bytes per stage: A 16KB + B 32KB
#define SA_OFF 0
#define SB_OFF 16384
#define NTHREADS 512           // 16 warps, warp grid 4x4, warp tile 32x64

// H is ~2e-6 (fp16 subnormal range) -> scale by 2^18, undo in epilogue.
#define H_SCALE   262144.0f
#define H_INVSCALE 3.814697265625e-06f

// ===================== Device scratch (no allocs allowed) =====================
__device__ __align__(256) __half g_A[(size_t)TOKENS * IN_F];   // fp16(x)
__device__ __align__(256) __half g_B[(size_t)OUT_F * IN_F];    // fp16(H^T * 2^18), K-major

// ===================== Helpers (base-target PTX only) =====================
__device__ __forceinline__ uint32_t smem_u32(const void* p) {
    uint32_t a;
    asm("{ .reg .u64 t; cvta.to.shared.u64 t, %1; cvt.u32.u64 %0, t; }" : "=r"(a) : "l"(p));
    return a;
}
__device__ __forceinline__ void cp_async16(uint32_t saddr, const void* g) {
    asm volatile("cp.async.cg.shared.global [%0], [%1], 16;" :: "r"(saddr), "l"(g) : "memory");
}
#define CP_COMMIT() asm volatile("cp.async.commit_group;" ::: "memory")
#define CP_WAIT(n)  asm volatile("cp.async.wait_group %0;" :: "n"(n) : "memory")

__device__ __forceinline__ void ldsm_x4(uint32_t* r, uint32_t addr) {
    asm volatile("ldmatrix.sync.aligned.m8n8.x4.shared.b16 {%0,%1,%2,%3}, [%4];"
                 : "=r"(r[0]), "=r"(r[1]), "=r"(r[2]), "=r"(r[3]) : "r"(addr));
}
__device__ __forceinline__ void mma16816(float* c, const uint32_t* a, const uint32_t* b) {
    asm volatile(
        "mma.sync.aligned.m16n8k16.row.col.f32.f16.f16.f32 "
        "{%0,%1,%2,%3}, {%4,%5,%6,%7}, {%8,%9}, {%0,%1,%2,%3};"
        : "+f"(c[0]), "+f"(c[1]), "+f"(c[2]), "+f"(c[3])
        : "r"(a[0]), "r"(a[1]), "r"(a[2]), "r"(a[3]), "r"(b[0]), "r"(b[1]));
}

// ===================== Kernel 1: convert x to fp16 =====================
__global__ void split_x_kernel(const float* __restrict__ x) {
    size_t i = (size_t)blockIdx.x * blockDim.x + threadIdx.x;  // float4 index
    float4 v = reinterpret_cast<const float4*>(x)[i];
    __half2* A = reinterpret_cast<__half2*>(g_A);
    A[2 * i + 0] = __halves2half2(__float2half_rn(v.x), __float2half_rn(v.y));
    A[2 * i + 1] = __halves2half2(__float2half_rn(v.z), __float2half_rn(v.w));
}

// ===================== Kernel 2: build H^T (K-major), scaled fp16 =====================
// Ht[n, k] = H[k, n] = sum_i rule[i, a, kq] * W[i, c, p],  k = a*512 + c, n = kq*2048 + p
__global__ void build_h_kernel(const float* __restrict__ rule, const float* __restrict__ W) {
    extern __shared__ float Ws[];  // [4][64][65] padded
    __shared__ float rs[64];
    const int t = threadIdx.x;          // 256 threads
    const int p0 = blockIdx.x * 64;     // out_per dim (2048)
    const int c0 = blockIdx.y * 64;     // in_per dim (512)

    for (int idx = t; idx < 4 * 64 * 64; idx += 256) {
        int i = idx >> 12;
        int cc = (idx >> 6) & 63;
        int pp = idx & 63;
        Ws[(i * 64 + cc) * 65 + pp] =
            W[(size_t)i * 512 * 2048 + (size_t)(c0 + cc) * 2048 + (p0 + pp)];
    }
    if (t < 64) rs[t] = rule[t];
    __syncthreads();

#pragma unroll
    for (int a = 0; a < 4; a++) {
#pragma unroll
        for (int kq = 0; kq < 4; kq++) {
            float r0 = rs[0 * 16 + a * 4 + kq];
            float r1 = rs[1 * 16 + a * 4 + kq];
            float r2 = rs[2 * 16 + a * 4 + kq];
            float r3 = rs[3 * 16 + a * 4 + kq];
#pragma unroll
            for (int e = 0; e < 16; e++) {
                int lin = e * 256 + t;
                int cc = lin & 63;
                int pp = lin >> 6;
                float v = r0 * Ws[(0 * 64 + cc) * 65 + pp]
                        + r1 * Ws[(1 * 64 + cc) * 65 + pp]
                        + r2 * Ws[(2 * 64 + cc) * 65 + pp]
                        + r3 * Ws[(3 * 64 + cc) * 65 + pp];
                size_t n = (size_t)(kq * 2048 + p0 + pp);
                size_t k = (size_t)(a * 512 + c0 + cc);
                g_B[n * IN_F + k] = __float2half_rn(v * H_SCALE);
            }
        }
    }
}

// ===================== Kernel 3: pipelined fp16 mma.sync GEMM, 16 warps =====================
// y = (x_fp16 @ (H*2^18)_fp16) * 2^-18 + b. Smem rows: 64 fp16 = 128B = 8x16B
// chunks, XOR swizzle chunk c ^= (row & 7). Warp grid 4x4, warp tile 32x64:
// 4 warps/SMSP cover LDSM latency + barrier skew with other warps' HMMAs.
__global__ void __launch_bounds__(NTHREADS, 1)
phm_gemm_kernel(float* __restrict__ y, const float* __restrict__ bias) {
    extern __shared__ char smem[];
    const uint32_t sb = smem_u32(smem);
    const int tid = threadIdx.x;
    const int wid = tid >> 5, lane = tid & 31;
    const int wm = wid >> 2, wn = wid & 3;     // 4 x 4 warp grid
    const int bn = blockIdx.x, bm = blockIdx.y;

    const __half* Ag = g_A + (size_t)bm * BM * IN_F;
    const __half* Bg = g_B + (size_t)bn * BN * IN_F;

    // ---- async loader for one K-chunk into a stage (512 threads) ----
    auto load_chunk = [&](int kc, int stg) {
        const uint32_t s = sb + stg * STG_SZ;
        const int kof = kc * BK;
#pragma unroll
        for (int u = 0; u < 2; u++) {            // A: 128 rows x 8 chunks = 1024
            int idx = u * NTHREADS + tid;
            int r = idx >> 3, c = idx & 7;
            uint32_t so = (uint32_t)(r * 128 + ((c ^ (r & 7)) * 16));
            cp_async16(s + SA_OFF + so, Ag + (size_t)r * IN_F + kof + c * 8);
        }
#pragma unroll
        for (int u = 0; u < 4; u++) {            // B: 256 rows x 8 chunks = 2048
            int idx = u * NTHREADS + tid;
            int r = idx >> 3, c = idx & 7;
            uint32_t so = (uint32_t)(r * 128 + ((c ^ (r & 7)) * 16));
            cp_async16(s + SB_OFF + so, Bg + (size_t)r * IN_F + kof + c * 8);
        }
    };

    // ---- prologue: fill STAGES-1 stages ----
#pragma unroll
    for (int p = 0; p < STAGES - 1; p++) {
        load_chunk(p, p);
        CP_COMMIT();
    }

    float acc[2][8][4];                          // warp tile 32x64
#pragma unroll
    for (int mf = 0; mf < 2; mf++)
#pragma unroll
        for (int n8 = 0; n8 < 8; n8++)
#pragma unroll
            for (int q = 0; q < 4; q++) acc[mf][n8][q] = 0.0f;

    // lane addressing for ldmatrix
    const int a_row = wm * 32 + (lane & 15);
    const int a_cpick = lane >> 4;                 // 0/1 -> k +0 / +8
    const int bg = lane >> 3;                      // 0..3
    const int b_row = wn * 64 + ((bg >> 1) << 3) + (lane & 7);
    const int b_cpick = bg & 1;

    for (int kc = 0; kc < NCHUNK; kc++) {
        CP_WAIT(STAGES - 2);
        __syncthreads();

        if (kc + STAGES - 1 < NCHUNK) load_chunk(kc + STAGES - 1, (kc + STAGES - 1) % STAGES);
        CP_COMMIT();

        const uint32_t s = sb + (kc % STAGES) * STG_SZ;
#pragma unroll
        for (int ks = 0; ks < 4; ks++) {          // 4 x k16 per 64-wide chunk
            uint32_t ah[2][4];
#pragma unroll
            for (int mf = 0; mf < 2; mf++) {
                int row = a_row + mf * 16;
                int cidx = ks * 2 + a_cpick;
                uint32_t ad = s + SA_OFF + (uint32_t)(row * 128 + ((cidx ^ (row & 7)) * 16));
                ldsm_x4(ah[mf], ad);
            }
#pragma unroll
            for (int nf2 = 0; nf2 < 4; nf2++) {
                int n = b_row + nf2 * 16;
                int cidx = ks * 2 + b_cpick;
                uint32_t bd = s + SB_OFF + (uint32_t)(n * 128 + ((cidx ^ (n & 7)) * 16));
                uint32_t bh[4];
                ldsm_x4(bh, bd);
#pragma unroll
                for (int mf = 0; mf < 2; mf++)
#pragma unroll
                    for (int nt = 0; nt < 2; nt++)
                        mma16816(acc[mf][nf2 * 2 + nt], ah[mf], &bh[nt * 2]);
            }
        }
    }

    // ---- epilogue: acc * 2^-18 + bias -> y, float2 stores ----
    const int row0 = bm * BM + wm * 32 + (lane >> 2);
    const int col0 = bn * BN + wn * 64 + (lane & 3) * 2;
#pragma unroll
    for (int mf = 0; mf < 2; mf++) {
#pragma unroll
        for (int n8 = 0; n8 < 8; n8++) {
            int col = col0 + n8 * 8;
            float b0 = bias[col], b1 = bias[col + 1];
            float* p0 = y + (size_t)(row0 + mf * 16) * OUT_F + col;
            float* p1 = y + (size_t)(row0 + mf * 16 + 8) * OUT_F + col;
            float2 v0 = make_float2(fmaf(acc[mf][n8][0], H_INVSCALE, b0),
                                    fmaf(acc[mf][n8][1], H_INVSCALE, b1));
            float2 v1 = make_float2(fmaf(acc[mf][n8][2], H_INVSCALE, b0),
                                    fmaf(acc[mf][n8][3], H_INVSCALE, b1));
            *reinterpret_cast<float2*>(p0) = v0;
            *reinterpret_cast<float2*>(p1) = v1;
        }
    }
}

// ===================== Launch =====================
extern "C" void kernel_launch(void* const* d_in, const int* in_sizes, int n_in,
                              void* d_out, int out_size) {
    const float* x    = (const float*)d_in[0];   // (8192, 2048)
    const float* rule = (const float*)d_in[1];   // (4, 4, 4)
    const float* W    = (const float*)d_in[2];   // (4, 512, 2048)
    const float* b    = (const float*)d_in[3];   // (8192,)
    float* y          = (float*)d_out;           // (8192, 8192)

    cudaFuncSetAttribute(build_h_kernel, cudaFuncAttributeMaxDynamicSharedMemorySize,
                         4 * 64 * 65 * 4);
    cudaFuncSetAttribute(phm_gemm_kernel, cudaFuncAttributeMaxDynamicSharedMemorySize,
                         STAGES * STG_SZ);

    // 1) x -> fp16
    split_x_kernel<<<16384, 256>>>(x);
    // 2) H^T (K-major), scaled by 2^18, fp16
    build_h_kernel<<<dim3(2048 / 64, 512 / 64), 256, 4 * 64 * 65 * 4>>>(rule, W);
    // 3) GEMM: y = x @ H + b, single fp16 term, 16 warps/CTA
    phm_gemm_kernel<<<dim3(OUT_F / BN, TOKENS / BM), NTHREADS, STAGES * STG_SZ>>>(y, b);
}

// round 7
// speedup vs baseline: 1.1492x; 1.1492x over previous
#include <cuda_runtime.h>
#include <cuda_bf16.h>
#include <cuda_fp16.h>
#include <cstdint>

// ===================== Problem constants =====================
#define TOKENS   8192
#define IN_F     2048
#define OUT_F    8192
#define BM 128
#define BN 128
#define BK 64                  // fp16 elems per K-chunk (128 bytes per row)
#define NCHUNK (IN_F / BK)     // 32
#define STAGES 3
#define STG_SZ 32768           // per stage: A 16KB + B 16KB
#define SA_OFF 0
#define SB_OFF 16384
#define NTHREADS 128           // 4 warps, warp grid 2x2, warp tile 64x64

// H is ~2e-6 (fp16 subnormal range) -> scale by 2^18, undo in epilogue.
#define H_SCALE   262144.0f
#define H_INVSCALE 3.814697265625e-06f

// ===================== Device scratch (no allocs allowed) =====================
__device__ __align__(256) __half g_A[(size_t)TOKENS * IN_F];   // fp16(x)
__device__ __align__(256) __half g_B[(size_t)OUT_F * IN_F];    // fp16(H^T * 2^18), K-major

// ===================== Helpers (base-target PTX only) =====================
__device__ __forceinline__ uint32_t smem_u32(const void* p) {
    uint32_t a;
    asm("{ .reg .u64 t; cvta.to.shared.u64 t, %1; cvt.u32.u64 %0, t; }" : "=r"(a) : "l"(p));
    return a;
}
__device__ __forceinline__ void cp_async16(uint32_t saddr, const void* g) {
    asm volatile("cp.async.cg.shared.global [%0], [%1], 16;" :: "r"(saddr), "l"(g) : "memory");
}
#define CP_COMMIT() asm volatile("cp.async.commit_group;" ::: "memory")
#define CP_WAIT(n)  asm volatile("cp.async.wait_group %0;" :: "n"(n) : "memory")

__device__ __forceinline__ void ldsm_x4(uint32_t* r, uint32_t addr) {
    asm volatile("ldmatrix.sync.aligned.m8n8.x4.shared.b16 {%0,%1,%2,%3}, [%4];"
                 : "=r"(r[0]), "=r"(r[1]), "=r"(r[2]), "=r"(r[3]) : "r"(addr));
}
__device__ __forceinline__ void mma16816(float* c, const uint32_t* a, const uint32_t* b) {
    asm volatile(
        "mma.sync.aligned.m16n8k16.row.col.f32.f16.f16.f32 "
        "{%0,%1,%2,%3}, {%4,%5,%6,%7}, {%8,%9}, {%0,%1,%2,%3};"
        : "+f"(c[0]), "+f"(c[1]), "+f"(c[2]), "+f"(c[3])
        : "r"(a[0]), "r"(a[1]), "r"(a[2]), "r"(a[3]), "r"(b[0]), "r"(b[1]));
}

// ===================== Kernel 1: convert x to fp16 =====================
__global__ void split_x_kernel(const float* __restrict__ x) {
    size_t i = (size_t)blockIdx.x * blockDim.x + threadIdx.x;  // float4 index
    float4 v = reinterpret_cast<const float4*>(x)[i];
    __half2* A = reinterpret_cast<__half2*>(g_A);
    A[2 * i + 0] = __halves2half2(__float2half_rn(v.x), __float2half_rn(v.y));
    A[2 * i + 1] = __halves2half2(__float2half_rn(v.z), __float2half_rn(v.w));
}

// ===================== Kernel 2: build H^T (K-major), scaled fp16 =====================
// Ht[n, k] = H[k, n] = sum_i rule[i, a, kq] * W[i, c, p],  k = a*512 + c, n = kq*2048 + p
__global__ void build_h_kernel(const float* __restrict__ rule, const float* __restrict__ W) {
    extern __shared__ float Ws[];  // [4][64][65] padded
    __shared__ float rs[64];
    const int t = threadIdx.x;          // 256 threads
    const int p0 = blockIdx.x * 64;     // out_per dim (2048)
    const int c0 = blockIdx.y * 64;     // in_per dim (512)

    for (int idx = t; idx < 4 * 64 * 64; idx += 256) {
        int i = idx >> 12;
        int cc = (idx >> 6) & 63;
        int pp = idx & 63;
        Ws[(i * 64 + cc) * 65 + pp] =
            W[(size_t)i * 512 * 2048 + (size_t)(c0 + cc) * 2048 + (p0 + pp)];
    }
    if (t < 64) rs[t] = rule[t];
    __syncthreads();

#pragma unroll
    for (int a = 0; a < 4; a++) {
#pragma unroll
        for (int kq = 0; kq < 4; kq++) {
            float r0 = rs[0 * 16 + a * 4 + kq];
            float r1 = rs[1 * 16 + a * 4 + kq];
            float r2 = rs[2 * 16 + a * 4 + kq];
            float r3 = rs[3 * 16 + a * 4 + kq];
#pragma unroll
            for (int e = 0; e < 16; e++) {
                int lin = e * 256 + t;
                int cc = lin & 63;
                int pp = lin >> 6;
                float v = r0 * Ws[(0 * 64 + cc) * 65 + pp]
                        + r1 * Ws[(1 * 64 + cc) * 65 + pp]
                        + r2 * Ws[(2 * 64 + cc) * 65 + pp]
                        + r3 * Ws[(3 * 64 + cc) * 65 + pp];
                size_t n = (size_t)(kq * 2048 + p0 + pp);
                size_t k = (size_t)(a * 512 + c0 + cc);
                g_B[n * IN_F + k] = __float2half_rn(v * H_SCALE);
            }
        }
    }
}

// ===================== Kernel 3: fp16 mma.sync GEMM, 2 CTAs/SM =====================
// 128x128 CTA tile, 4 warps (warp tile 64x64), 3-stage cp.async pipeline,
// 96KB smem -> 2 co-resident CTAs per SM so one CTA's MMAs cover the other's
// barrier / cp.async-wait / prologue / epilogue bubbles.
// Smem rows: 64 fp16 = 128B = 8 x 16B chunks, XOR swizzle chunk c ^= (row & 7).
__global__ void __launch_bounds__(NTHREADS, 2)
phm_gemm_kernel(float* __restrict__ y, const float* __restrict__ bias) {
    extern __shared__ char smem[];
    const uint32_t sb = smem_u32(smem);
    const int tid = threadIdx.x;
    const int wid = tid >> 5, lane = tid & 31;
    const int wm = wid >> 1, wn = wid & 1;     // 2 x 2 warp grid
    const int bn = blockIdx.x, bm = blockIdx.y;

    const __half* Ag = g_A + (size_t)bm * BM * IN_F;
    const __half* Bg = g_B + (size_t)bn * BN * IN_F;

    // ---- async loader for one K-chunk into a stage (128 threads) ----
    auto load_chunk = [&](int kc, int stg) {
        const uint32_t s = sb + stg * STG_SZ;
        const int kof = kc * BK;
#pragma unroll
        for (int u = 0; u < 8; u++) {            // A: 128 rows x 8 chunks = 1024
            int idx = u * NTHREADS + tid;
            int r = idx >> 3, c = idx & 7;
            uint32_t so = (uint32_t)(r * 128 + ((c ^ (r & 7)) * 16));
            cp_async16(s + SA_OFF + so, Ag + (size_t)r * IN_F + kof + c * 8);
        }
#pragma unroll
        for (int u = 0; u < 8; u++) {            // B: 128 rows x 8 chunks = 1024
            int idx = u * NTHREADS + tid;
            int r = idx >> 3, c = idx & 7;
            uint32_t so = (uint32_t)(r * 128 + ((c ^ (r & 7)) * 16));
            cp_async16(s + SB_OFF + so, Bg + (size_t)r * IN_F + kof + c * 8);
        }
    };

    // ---- prologue: fill STAGES-1 stages ----
#pragma unroll
    for (int p = 0; p < STAGES - 1; p++) {
        load_chunk(p, p);
        CP_COMMIT();
    }

    float acc[4][8][4];                          // warp tile 64x64
#pragma unroll
    for (int mf = 0; mf < 4; mf++)
#pragma unroll
        for (int n8 = 0; n8 < 8; n8++)
#pragma unroll
            for (int q = 0; q < 4; q++) acc[mf][n8][q] = 0.0f;

    // lane addressing for ldmatrix
    const int a_row = wm * 64 + (lane & 15);
    const int a_cpick = lane >> 4;                 // 0/1 -> k +0 / +8
    const int bg = lane >> 3;                      // 0..3
    const int b_row = wn * 64 + ((bg >> 1) << 3) + (lane & 7);
    const int b_cpick = bg & 1;

    for (int kc = 0; kc < NCHUNK; kc++) {
        CP_WAIT(STAGES - 2);
        __syncthreads();

        if (kc + STAGES - 1 < NCHUNK) load_chunk(kc + STAGES - 1, (kc + STAGES - 1) % STAGES);
        CP_COMMIT();

        const uint32_t s = sb + (kc % STAGES) * STG_SZ;
#pragma unroll
        for (int ks = 0; ks < 4; ks++) {          // 4 x k16 per 64-wide chunk
            uint32_t ah[4][4];
#pragma unroll
            for (int mf = 0; mf < 4; mf++) {
                int row = a_row + mf * 16;
                int cidx = ks * 2 + a_cpick;
                uint32_t ad = s + SA_OFF + (uint32_t)(row * 128 + ((cidx ^ (row & 7)) * 16));
                ldsm_x4(ah[mf], ad);
            }
#pragma unroll
            for (int nf2 = 0; nf2 < 4; nf2++) {
                int n = b_row + nf2 * 16;
                int cidx = ks * 2 + b_cpick;
                uint32_t bd = s + SB_OFF + (uint32_t)(n * 128 + ((cidx ^ (n & 7)) * 16));
                uint32_t bh[4];
                ldsm_x4(bh, bd);
#pragma unroll
                for (int mf = 0; mf < 4; mf++)
#pragma unroll
                    for (int nt = 0; nt < 2; nt++)
                        mma16816(acc[mf][nf2 * 2 + nt], ah[mf], &bh[nt * 2]);
            }
        }
    }

    // ---- epilogue: acc * 2^-18 + bias -> y, float2 stores ----
    const int row0 = bm * BM + wm * 64 + (lane >> 2);
    const int col0 = bn * BN + wn * 64 + (lane & 3) * 2;
#pragma unroll
    for (int mf = 0; mf < 4; mf++) {
#pragma unroll
        for (int n8 = 0; n8 < 8; n8++) {
            int col = col0 + n8 * 8;
            float b0 = bias[col], b1 = bias[col + 1];
            float* p0 = y + (size_t)(row0 + mf * 16) * OUT_F + col;
            float* p1 = y + (size_t)(row0 + mf * 16 + 8) * OUT_F + col;
            float2 v0 = make_float2(fmaf(acc[mf][n8][0], H_INVSCALE, b0),
                                    fmaf(acc[mf][n8][1], H_INVSCALE, b1));
            float2 v1 = make_float2(fmaf(acc[mf][n8][2], H_INVSCALE, b0),
                                    fmaf(acc[mf][n8][3], H_INVSCALE, b1));
            *reinterpret_cast<float2*>(p0) = v0;
            *reinterpret_cast<float2*>(p1) = v1;
        }
    }
}

// ===================== Launch =====================
extern "C" void kernel_launch(void* const* d_in, const int* in_sizes, int n_in,
                              void* d_out, int out_size) {
    const float* x    = (const float*)d_in[0];   // (8192, 2048)
    const float* rule = (const float*)d_in[1];   // (4, 4, 4)
    const float* W    = (const float*)d_in[2];   // (4, 512, 2048)
    const float* b    = (const float*)d_in[3];   // (8192,)
    float* y          = (float*)d_out;           // (8192, 8192)

    cudaFuncSetAttribute(build_h_kernel, cudaFuncAttributeMaxDynamicSharedMemorySize,
                         4 * 64 * 65 * 4);
    cudaFuncSetAttribute(phm_gemm_kernel, cudaFuncAttributeMaxDynamicSharedMemorySize,
                         STAGES * STG_SZ);

    // 1) x -> fp16
    split_x_kernel<<<16384, 256>>>(x);
    // 2) H^T (K-major), scaled by 2^18, fp16
    build_h_kernel<<<dim3(2048 / 64, 512 / 64), 256, 4 * 64 * 65 * 4>>>(rule, W);
    // 3) GEMM: y = x @ H + b, single fp16 term, 2 CTAs/SM
    phm_gemm_kernel<<<dim3(OUT_F / BN, TOKENS / BM), NTHREADS, STAGES * STG_SZ>>>(y, b);
}

// round 8
// speedup vs baseline: 1.1781x; 1.0252x over previous
#include <cuda_runtime.h>
#include <cuda_bf16.h>
#include <cuda_fp16.h>
#include <cstdint>

// ===================== Problem constants =====================
#define TOKENS   8192
#define IN_F     2048
#define OUT_F    8192
#define BM 128
#define BN 128
#define BK 64                  // fp16 elems per K-chunk
#define NCHUNK (IN_F / BK)     // 32
#define STAGES 3
// Tiled global layout: tile (b, kc) = 128 rows x 72 halfs (64 data + 8 pad = 144B pitch)
#define ROWP    72             // halfs per row in tiled layout
#define ROWP_B  144            // bytes per row
#define TILE_H  (128 * ROWP)   // halfs per tile (9216)
#define TILE_B  (128 * ROWP_B) // bytes per tile (18432)
#define STG_SZ  (2 * TILE_B)   // A tile + B tile per stage (36864)
#define SA_OFF  0
#define SB_OFF  TILE_B
#define SM_HDR  128            // mbarriers live in [0, 128)
#define NTHREADS 128           // 4 warps, warp grid 2x2, warp tile 64x64

// H is ~2e-6 (fp16 subnormal range) -> scale by 2^18, undo in epilogue.
#define H_SCALE   262144.0f
#define H_INVSCALE 3.814697265625e-06f

// ===================== Device scratch (no allocs allowed) =====================
// Tile-major: [b][kc][row][col(+pad)]
__device__ __align__(256) __half g_A[(size_t)(TOKENS / 128) * NCHUNK * TILE_H];
__device__ __align__(256) __half g_B[(size_t)(OUT_F / 128) * NCHUNK * TILE_H];

// ===================== Helpers (base-target PTX: sm_80/sm_90 era) =====================
__device__ __forceinline__ uint32_t smem_u32(const void* p) {
    uint32_t a;
    asm("{ .reg .u64 t; cvta.to.shared.u64 t, %1; cvt.u32.u64 %0, t; }" : "=r"(a) : "l"(p));
    return a;
}
__device__ __forceinline__ void ldsm_x4(uint32_t* r, uint32_t addr) {
    asm volatile("ldmatrix.sync.aligned.m8n8.x4.shared.b16 {%0,%1,%2,%3}, [%4];"
                 : "=r"(r[0]), "=r"(r[1]), "=r"(r[2]), "=r"(r[3]) : "r"(addr));
}
__device__ __forceinline__ void mma16816(float* c, const uint32_t* a, const uint32_t* b) {
    asm volatile(
        "mma.sync.aligned.m16n8k16.row.col.f32.f16.f16.f32 "
        "{%0,%1,%2,%3}, {%4,%5,%6,%7}, {%8,%9}, {%0,%1,%2,%3};"
        : "+f"(c[0]), "+f"(c[1]), "+f"(c[2]), "+f"(c[3])
        : "r"(a[0]), "r"(a[1]), "r"(a[2]), "r"(a[3]), "r"(b[0]), "r"(b[1]));
}
// Bulk async copy global->shared with mbarrier transaction accounting (sm_90 base)
__device__ __forceinline__ void bulk_cp(uint32_t dst, const void* src, uint32_t bytes,
                                        uint32_t mbar) {
    asm volatile(
        "cp.async.bulk.shared::cluster.global.mbarrier::complete_tx::bytes [%0], [%1], %2, [%3];"
        :: "r"(dst), "l"(src), "r"(bytes), "r"(mbar) : "memory");
}
#define MBAR_INIT(m, cnt) \
    asm volatile("mbarrier.init.shared.b64 [%0], %1;" :: "r"((uint32_t)(m)), "r"((uint32_t)(cnt)) : "memory")
#define MBAR_EXPECT_TX(m, bytes) \
    asm volatile("mbarrier.arrive.expect_tx.shared.b64 _, [%0], %1;" \
                 :: "r"((uint32_t)(m)), "r"((uint32_t)(bytes)) : "memory")
#define MBAR_WAIT_PARITY(mbar, parity) do {                                               \
    uint32_t _m = (uint32_t)(mbar);                                                       \
    uint32_t _p = (uint32_t)(parity);                                                     \
    uint32_t _done;                                                                       \
    asm volatile("{\n\t.reg .pred p;\n\t"                                                 \
        "mbarrier.try_wait.parity.acquire.cta.shared::cta.b64 p, [%1], %2;\n\t"           \
        "selp.b32 %0, 1, 0, p;\n\t}"                                                      \
        : "=r"(_done) : "r"(_m), "r"(_p) : "memory");                                     \
    if (!_done) {                                                                         \
        asm volatile("{\n\t.reg .pred P1;\n\t"                                            \
            "WL_%=:\n\t"                                                                  \
            "mbarrier.try_wait.parity.acquire.cta.shared::cta.b64 P1, [%0], %1, 0x989680;\n\t" \
            "@P1 bra.uni WD_%=;\n\t"                                                      \
            "bra.uni WL_%=;\n\t"                                                          \
            "WD_%=:\n\t}"                                                                 \
            :: "r"(_m), "r"(_p) : "memory");                                              \
    }                                                                                     \
} while (0)

// ===================== Kernel 1: x -> fp16, tile-major 144B-pitch layout =====================
__global__ void split_x_kernel(const float* __restrict__ x) {
    size_t i = (size_t)blockIdx.x * blockDim.x + threadIdx.x;  // float4 index
    float4 v = reinterpret_cast<const float4*>(x)[i];
    int m  = (int)(i >> 9);             // i / (IN_F/4)
    int k  = ((int)i & 511) * 4;
    int bm = m >> 7, row = m & 127;
    int kc = k >> 6, col = k & 63;
    size_t off = ((size_t)(bm * NCHUNK + kc) * 128 + row) * ROWP + col;
    __half2* dst = reinterpret_cast<__half2*>(g_A + off);
    dst[0] = __halves2half2(__float2half_rn(v.x), __float2half_rn(v.y));
    dst[1] = __halves2half2(__float2half_rn(v.z), __float2half_rn(v.w));
}

// ===================== Kernel 2: build H^T (K-major), scaled fp16, tiled layout =====================
// Ht[n, k] = sum_i rule[i, a, kq] * W[i, c, p],  k = a*512 + c, n = kq*2048 + p
__global__ void build_h_kernel(const float* __restrict__ rule, const float* __restrict__ W) {
    extern __shared__ float Ws[];  // [4][64][65] padded
    __shared__ float rs[64];
    const int t = threadIdx.x;          // 256 threads
    const int p0 = blockIdx.x * 64;     // out_per dim (2048)
    const int c0 = blockIdx.y * 64;     // in_per dim (512)

    for (int idx = t; idx < 4 * 64 * 64; idx += 256) {
        int i = idx >> 12;
        int cc = (idx >> 6) & 63;
        int pp = idx & 63;
        Ws[(i * 64 + cc) * 65 + pp] =
            W[(size_t)i * 512 * 2048 + (size_t)(c0 + cc) * 2048 + (p0 + pp)];
    }
    if (t < 64) rs[t] = rule[t];
    __syncthreads();

#pragma unroll
    for (int a = 0; a < 4; a++) {
#pragma unroll
        for (int kq = 0; kq < 4; kq++) {
            float r0 = rs[0 * 16 + a * 4 + kq];
            float r1 = rs[1 * 16 + a * 4 + kq];
            float r2 = rs[2 * 16 + a * 4 + kq];
            float r3 = rs[3 * 16 + a * 4 + kq];
#pragma unroll
            for (int e = 0; e < 16; e++) {
                int lin = e * 256 + t;
                int cc = lin & 63;
                int pp = lin >> 6;
                float v = r0 * Ws[(0 * 64 + cc) * 65 + pp]
                        + r1 * Ws[(1 * 64 + cc) * 65 + pp]
                        + r2 * Ws[(2 * 64 + cc) * 65 + pp]
                        + r3 * Ws[(3 * 64 + cc) * 65 + pp];
                int n = kq * 2048 + p0 + pp;
                int k = a * 512 + c0 + cc;
                int bn = n >> 7, row = n & 127;
                int kc = k >> 6, col = k & 63;
                g_B[((size_t)(bn * NCHUNK + kc) * 128 + row) * ROWP + col] =
                    __float2half_rn(v * H_SCALE);
            }
        }
    }
}

// ===================== Kernel 3: fp16 mma.sync GEMM, bulk-copy pipeline, 2 CTAs/SM =====================
// 128x128 CTA tile, 4 warps (64x64 warp tiles), 3-stage pipeline fed by ONE
// cp.async.bulk per tile per chunk (issued by thread 0) -> LSU carries only
// LDSM traffic. 144B row pitch keeps ldmatrix conflict-free without XOR.
__global__ void __launch_bounds__(NTHREADS, 2)
phm_gemm_kernel(float* __restrict__ y, const float* __restrict__ bias) {
    extern __shared__ char smem[];
    const uint32_t sb = smem_u32(smem);
    const int tid = threadIdx.x;
    const int wid = tid >> 5, lane = tid & 31;
    const int wm = wid >> 1, wn = wid & 1;     // 2 x 2 warp grid
    const int bn = blockIdx.x, bm = blockIdx.y;

    const __half* At = g_A + (size_t)bm * NCHUNK * TILE_H;
    const __half* Bt = g_B + (size_t)bn * NCHUNK * TILE_H;

    if (tid == 0) {
        MBAR_INIT(sb + 0, 1);
        MBAR_INIT(sb + 8, 1);
        MBAR_INIT(sb + 16, 1);
    }
    __syncthreads();

    // prologue: fill stages 0..STAGES-2
    if (tid == 0) {
#pragma unroll
        for (int p = 0; p < STAGES - 1; p++) {
            uint32_t mb = sb + p * 8;
            uint32_t s = sb + SM_HDR + p * STG_SZ;
            MBAR_EXPECT_TX(mb, STG_SZ);
            bulk_cp(s + SA_OFF, At + (size_t)p * TILE_H, TILE_B, mb);
            bulk_cp(s + SB_OFF, Bt + (size_t)p * TILE_H, TILE_B, mb);
        }
    }

    float acc[4][8][4];                          // warp tile 64x64
#pragma unroll
    for (int mf = 0; mf < 4; mf++)
#pragma unroll
        for (int n8 = 0; n8 < 8; n8++)
#pragma unroll
            for (int q = 0; q < 4; q++) acc[mf][n8][q] = 0.0f;

    // lane addressing for ldmatrix
    const int a_row = wm * 64 + (lane & 15);
    const int a_cpick = lane >> 4;                 // 0/1 -> k +0 / +8
    const int bg = lane >> 3;                      // 0..3
    const int b_row = wn * 64 + ((bg >> 1) << 3) + (lane & 7);
    const int b_cpick = bg & 1;

    int stg = 0, ph = 0;
    for (int kc = 0; kc < NCHUNK; kc++) {
        MBAR_WAIT_PARITY(sb + stg * 8, ph);
        __syncthreads();   // all warps finished reading the stage we refill below

        if (tid == 0 && kc + STAGES - 1 < NCHUNK) {
            int ns = stg + STAGES - 1; if (ns >= STAGES) ns -= STAGES;
            uint32_t mb = sb + ns * 8;
            uint32_t d = sb + SM_HDR + ns * STG_SZ;
            MBAR_EXPECT_TX(mb, STG_SZ);
            bulk_cp(d + SA_OFF, At + (size_t)(kc + STAGES - 1) * TILE_H, TILE_B, mb);
            bulk_cp(d + SB_OFF, Bt + (size_t)(kc + STAGES - 1) * TILE_H, TILE_B, mb);
        }

        const uint32_t s = sb + SM_HDR + stg * STG_SZ;
#pragma unroll
        for (int ks = 0; ks < 4; ks++) {          // 4 x k16 per 64-wide chunk
            uint32_t ah[4][4];
#pragma unroll
            for (int mf = 0; mf < 4; mf++) {
                int row = a_row + mf * 16;
                int cidx = ks * 2 + a_cpick;
                uint32_t ad = s + SA_OFF + (uint32_t)(row * ROWP_B + cidx * 16);
                ldsm_x4(ah[mf], ad);
            }
#pragma unroll
            for (int nf2 = 0; nf2 < 4; nf2++) {
                int n = b_row + nf2 * 16;
                int cidx = ks * 2 + b_cpick;
                uint32_t bd = s + SB_OFF + (uint32_t)(n * ROWP_B + cidx * 16);
                uint32_t bh[4];
                ldsm_x4(bh, bd);
#pragma unroll
                for (int mf = 0; mf < 4; mf++)
#pragma unroll
                    for (int nt = 0; nt < 2; nt++)
                        mma16816(acc[mf][nf2 * 2 + nt], ah[mf], &bh[nt * 2]);
            }
        }
        if (++stg == STAGES) { stg = 0; ph ^= 1; }
    }

    // ---- epilogue: acc * 2^-18 + bias -> y, float2 stores ----
    const int row0 = bm * BM + wm * 64 + (lane >> 2);
    const int col0 = bn * BN + wn * 64 + (lane & 3) * 2;
#pragma unroll
    for (int mf = 0; mf < 4; mf++) {
#pragma unroll
        for (int n8 = 0; n8 < 8; n8++) {
            int col = col0 + n8 * 8;
            float b0 = bias[col], b1 = bias[col + 1];
            float* p0 = y + (size_t)(row0 + mf * 16) * OUT_F + col;
            float* p1 = y + (size_t)(row0 + mf * 16 + 8) * OUT_F + col;
            float2 v0 = make_float2(fmaf(acc[mf][n8][0], H_INVSCALE, b0),
                                    fmaf(acc[mf][n8][1], H_INVSCALE, b1));
            float2 v1 = make_float2(fmaf(acc[mf][n8][2], H_INVSCALE, b0),
                                    fmaf(acc[mf][n8][3], H_INVSCALE, b1));
            *reinterpret_cast<float2*>(p0) = v0;
            *reinterpret_cast<float2*>(p1) = v1;
        }
    }
}

// ===================== Launch =====================
extern "C" void kernel_launch(void* const* d_in, const int* in_sizes, int n_in,
                              void* d_out, int out_size) {
    const float* x    = (const float*)d_in[0];   // (8192, 2048)
    const float* rule = (const float*)d_in[1];   // (4, 4, 4)
    const float* W    = (const float*)d_in[2];   // (4, 512, 2048)
    const float* b    = (const float*)d_in[3];   // (8192,)
    float* y          = (float*)d_out;           // (8192, 8192)

    cudaFuncSetAttribute(build_h_kernel, cudaFuncAttributeMaxDynamicSharedMemorySize,
                         4 * 64 * 65 * 4);
    cudaFuncSetAttribute(phm_gemm_kernel, cudaFuncAttributeMaxDynamicSharedMemorySize,
                         SM_HDR + STAGES * STG_SZ);

    // 1) x -> fp16 (tile-major, 144B pitch)
    split_x_kernel<<<16384, 256>>>(x);
    // 2) H^T (K-major), scaled by 2^18, fp16 (tile-major, 144B pitch)
    build_h_kernel<<<dim3(2048 / 64, 512 / 64), 256, 4 * 64 * 65 * 4>>>(rule, W);
    // 3) GEMM: y = x @ H + b, bulk-copy pipeline, 2 CTAs/SM
    phm_gemm_kernel<<<dim3(OUT_F / BN, TOKENS / BM), NTHREADS,
                      SM_HDR + STAGES * STG_SZ>>>(y, b);
}

// round 9
// speedup vs baseline: 1.2383x; 1.0510x over previous
#include <cuda_runtime.h>
#include <cuda_bf16.h>
#include <cuda_fp16.h>
#include <cstdint>

// ===================== Problem constants =====================
#define TOKENS   8192
#define IN_F     2048
#define OUT_F    8192
#define BM 128
#define BN 128
#define BK 64                  // fp16 elems per K-chunk
#define NCHUNK (IN_F / BK)     // 32
#define STAGES 3
// Tiled global layout, PRE-SWIZZLED: tile (b, kc) = 128 rows x 64 halfs (128B pitch).
// Within each 128B row, 16B chunk c lives at position c ^ (row & 7)  -> ldmatrix
// conflict-free in smem after a raw bulk copy, and prologue writes stay coalesced
// (permutation never leaves the 128B segment).
#define TILE_H  (128 * 64)     // halfs per tile (8192)
#define TILE_B  (128 * 128)    // bytes per tile (16384)
#define STG_SZ  (2 * TILE_B)   // A tile + B tile per stage (32768)
#define SA_OFF  0
#define SB_OFF  TILE_B
#define SM_HDR  128            // mbarriers live in [0, 128)
#define NTHREADS 128           // 4 warps, warp grid 2x2, warp tile 64x64

// H is ~2e-6 (fp16 subnormal range) -> scale by 2^18, undo in epilogue.
#define H_SCALE   262144.0f
#define H_INVSCALE 3.814697265625e-06f

// ===================== Device scratch (no allocs allowed) =====================
// Tile-major: [b][kc][row][swizzled 16B chunks]
__device__ __align__(256) __half g_A[(size_t)(TOKENS / 128) * NCHUNK * TILE_H];
__device__ __align__(256) __half g_B[(size_t)(OUT_F / 128) * NCHUNK * TILE_H];

// ===================== Helpers (base-target PTX: sm_80/sm_90 era) =====================
__device__ __forceinline__ uint32_t smem_u32(const void* p) {
    uint32_t a;
    asm("{ .reg .u64 t; cvta.to.shared.u64 t, %1; cvt.u32.u64 %0, t; }" : "=r"(a) : "l"(p));
    return a;
}
__device__ __forceinline__ void ldsm_x4(uint32_t* r, uint32_t addr) {
    asm volatile("ldmatrix.sync.aligned.m8n8.x4.shared.b16 {%0,%1,%2,%3}, [%4];"
                 : "=r"(r[0]), "=r"(r[1]), "=r"(r[2]), "=r"(r[3]) : "r"(addr));
}
__device__ __forceinline__ void mma16816(float* c, const uint32_t* a, const uint32_t* b) {
    asm volatile(
        "mma.sync.aligned.m16n8k16.row.col.f32.f16.f16.f32 "
        "{%0,%1,%2,%3}, {%4,%5,%6,%7}, {%8,%9}, {%0,%1,%2,%3};"
        : "+f"(c[0]), "+f"(c[1]), "+f"(c[2]), "+f"(c[3])
        : "r"(a[0]), "r"(a[1]), "r"(a[2]), "r"(a[3]), "r"(b[0]), "r"(b[1]));
}
// Bulk async copy global->shared with mbarrier transaction accounting (sm_90 base)
__device__ __forceinline__ void bulk_cp(uint32_t dst, const void* src, uint32_t bytes,
                                        uint32_t mbar) {
    asm volatile(
        "cp.async.bulk.shared::cluster.global.mbarrier::complete_tx::bytes [%0], [%1], %2, [%3];"
        :: "r"(dst), "l"(src), "r"(bytes), "r"(mbar) : "memory");
}
#define MBAR_INIT(m, cnt) \
    asm volatile("mbarrier.init.shared.b64 [%0], %1;" :: "r"((uint32_t)(m)), "r"((uint32_t)(cnt)) : "memory")
#define MBAR_EXPECT_TX(m, bytes) \
    asm volatile("mbarrier.arrive.expect_tx.shared.b64 _, [%0], %1;" \
                 :: "r"((uint32_t)(m)), "r"((uint32_t)(bytes)) : "memory")
#define MBAR_WAIT_PARITY(mbar, parity) do {                                               \
    uint32_t _m = (uint32_t)(mbar);                                                       \
    uint32_t _p = (uint32_t)(parity);                                                     \
    uint32_t _done;                                                                       \
    asm volatile("{\n\t.reg .pred p;\n\t"                                                 \
        "mbarrier.try_wait.parity.acquire.cta.shared::cta.b64 p, [%1], %2;\n\t"           \
        "selp.b32 %0, 1, 0, p;\n\t}"                                                      \
        : "=r"(_done) : "r"(_m), "r"(_p) : "memory");                                     \
    if (!_done) {                                                                         \
        asm volatile("{\n\t.reg .pred P1;\n\t"                                            \
            "WL_%=:\n\t"                                                                  \
            "mbarrier.try_wait.parity.acquire.cta.shared::cta.b64 P1, [%0], %1, 0x989680;\n\t" \
            "@P1 bra.uni WD_%=;\n\t"                                                      \
            "bra.uni WL_%=;\n\t"                                                          \
            "WD_%=:\n\t}"                                                                 \
            :: "r"(_m), "r"(_p) : "memory");                                              \
    }                                                                                     \
} while (0)

// ===================== Kernel 1: x -> fp16, pre-swizzled tiled layout =====================
// One thread = 8 consecutive floats = one 16B fp16 chunk at its swizzled slot.
__global__ void split_x_kernel(const float* __restrict__ x) {
    size_t j = (size_t)blockIdx.x * blockDim.x + threadIdx.x;  // 8-float group index
    const float4* xp = reinterpret_cast<const float4*>(x) + 2 * j;
    float4 v0 = xp[0], v1 = xp[1];
    int m  = (int)(j >> 8);             // 256 groups per row (2048/8)
    int k  = ((int)j & 255) * 8;
    int bm = m >> 7, row = m & 127;
    int kc = k >> 6, col = k & 63;      // col multiple of 8
    int swc = (col >> 3) ^ (row & 7);
    size_t off = ((size_t)(bm * NCHUNK + kc) * 128 + row) * 64 + swc * 8;
    union { uint4 u; __half2 h[4]; } pk;
    pk.h[0] = __halves2half2(__float2half_rn(v0.x), __float2half_rn(v0.y));
    pk.h[1] = __halves2half2(__float2half_rn(v0.z), __float2half_rn(v0.w));
    pk.h[2] = __halves2half2(__float2half_rn(v1.x), __float2half_rn(v1.y));
    pk.h[3] = __halves2half2(__float2half_rn(v1.z), __float2half_rn(v1.w));
    *reinterpret_cast<uint4*>(g_A + off) = pk.u;
}

// ===================== Kernel 2: build H^T (K-major), scaled fp16, swizzled tiles =====================
// Ht[n, k] = sum_i rule[i, a, kq] * W[i, c, p],  k = a*512 + c, n = kq*2048 + p
__global__ void build_h_kernel(const float* __restrict__ rule, const float* __restrict__ W) {
    extern __shared__ float Ws[];  // [4][64][65] padded
    __shared__ float rs[64];
    const int t = threadIdx.x;          // 256 threads
    const int p0 = blockIdx.x * 64;     // out_per dim (2048)
    const int c0 = blockIdx.y * 64;     // in_per dim (512)

    for (int idx = t; idx < 4 * 64 * 64; idx += 256) {
        int i = idx >> 12;
        int cc = (idx >> 6) & 63;
        int pp = idx & 63;
        Ws[(i * 64 + cc) * 65 + pp] =
            W[(size_t)i * 512 * 2048 + (size_t)(c0 + cc) * 2048 + (p0 + pp)];
    }
    if (t < 64) rs[t] = rule[t];
    __syncthreads();

#pragma unroll
    for (int a = 0; a < 4; a++) {
#pragma unroll
        for (int kq = 0; kq < 4; kq++) {
            float r0 = rs[0 * 16 + a * 4 + kq];
            float r1 = rs[1 * 16 + a * 4 + kq];
            float r2 = rs[2 * 16 + a * 4 + kq];
            float r3 = rs[3 * 16 + a * 4 + kq];
#pragma unroll
            for (int e = 0; e < 16; e++) {
                int lin = e * 256 + t;
                int cc = lin & 63;
                int pp = lin >> 6;
                float v = r0 * Ws[(0 * 64 + cc) * 65 + pp]
                        + r1 * Ws[(1 * 64 + cc) * 65 + pp]
                        + r2 * Ws[(2 * 64 + cc) * 65 + pp]
                        + r3 * Ws[(3 * 64 + cc) * 65 + pp];
                int n = kq * 2048 + p0 + pp;
                int k = a * 512 + c0 + cc;
                int bn = n >> 7, row = n & 127;
                int kc = k >> 6, col = k & 63;
                int swcol = (((col >> 3) ^ (row & 7)) << 3) | (col & 7);
                g_B[((size_t)(bn * NCHUNK + kc) * 128 + row) * 64 + swcol] =
                    __float2half_rn(v * H_SCALE);
            }
        }
    }
}

// ===================== Kernel 3: fp16 mma.sync GEMM, bulk-copy pipeline, 2 CTAs/SM =====================
// 128x128 CTA tile, 4 warps (64x64 warp tiles), 3-stage pipeline fed by ONE
// 16KB cp.async.bulk per tile per chunk. Smem rows 128B, XOR-swizzled chunks
// (pre-baked in the global layout) -> conflict-free ldmatrix.
__global__ void __launch_bounds__(NTHREADS, 2)
phm_gemm_kernel(float* __restrict__ y, const float* __restrict__ bias) {
    extern __shared__ char smem[];
    const uint32_t sb = smem_u32(smem);
    const int tid = threadIdx.x;
    const int wid = tid >> 5, lane = tid & 31;
    const int wm = wid >> 1, wn = wid & 1;     // 2 x 2 warp grid
    const int bn = blockIdx.x, bm = blockIdx.y;

    const __half* At = g_A + (size_t)bm * NCHUNK * TILE_H;
    const __half* Bt = g_B + (size_t)bn * NCHUNK * TILE_H;

    if (tid == 0) {
        MBAR_INIT(sb + 0, 1);
        MBAR_INIT(sb + 8, 1);
        MBAR_INIT(sb + 16, 1);
    }
    __syncthreads();

    // prologue: fill stages 0..STAGES-2
    if (tid == 0) {
#pragma unroll
        for (int p = 0; p < STAGES - 1; p++) {
            uint32_t mb = sb + p * 8;
            uint32_t s = sb + SM_HDR + p * STG_SZ;
            MBAR_EXPECT_TX(mb, STG_SZ);
            bulk_cp(s + SA_OFF, At + (size_t)p * TILE_H, TILE_B, mb);
            bulk_cp(s + SB_OFF, Bt + (size_t)p * TILE_H, TILE_B, mb);
        }
    }

    float acc[4][8][4];                          // warp tile 64x64
#pragma unroll
    for (int mf = 0; mf < 4; mf++)
#pragma unroll
        for (int n8 = 0; n8 < 8; n8++)
#pragma unroll
            for (int q = 0; q < 4; q++) acc[mf][n8][q] = 0.0f;

    // lane addressing for ldmatrix
    const int a_row = wm * 64 + (lane & 15);
    const int a_cpick = lane >> 4;                 // 0/1 -> k +0 / +8
    const int bg = lane >> 3;                      // 0..3
    const int b_row = wn * 64 + ((bg >> 1) << 3) + (lane & 7);
    const int b_cpick = bg & 1;

    int stg = 0, ph = 0;
    for (int kc = 0; kc < NCHUNK; kc++) {
        MBAR_WAIT_PARITY(sb + stg * 8, ph);
        __syncthreads();   // all warps done reading the stage refilled below

        if (tid == 0 && kc + STAGES - 1 < NCHUNK) {
            int ns = stg + STAGES - 1; if (ns >= STAGES) ns -= STAGES;
            uint32_t mb = sb + ns * 8;
            uint32_t d = sb + SM_HDR + ns * STG_SZ;
            MBAR_EXPECT_TX(mb, STG_SZ);
            bulk_cp(d + SA_OFF, At + (size_t)(kc + STAGES - 1) * TILE_H, TILE_B, mb);
            bulk_cp(d + SB_OFF, Bt + (size_t)(kc + STAGES - 1) * TILE_H, TILE_B, mb);
        }

        const uint32_t s = sb + SM_HDR + stg * STG_SZ;
#pragma unroll
        for (int ks = 0; ks < 4; ks++) {          // 4 x k16 per 64-wide chunk
            uint32_t ah[4][4];
#pragma unroll
            for (int mf = 0; mf < 4; mf++) {
                int row = a_row + mf * 16;
                int cidx = ks * 2 + a_cpick;
                uint32_t ad = s + SA_OFF + (uint32_t)(row * 128 + ((cidx ^ (row & 7)) * 16));
                ldsm_x4(ah[mf], ad);
            }
#pragma unroll
            for (int nf2 = 0; nf2 < 4; nf2++) {
                int n = b_row + nf2 * 16;
                int cidx = ks * 2 + b_cpick;
                uint32_t bd = s + SB_OFF + (uint32_t)(n * 128 + ((cidx ^ (n & 7)) * 16));
                uint32_t bh[4];
                ldsm_x4(bh, bd);
#pragma unroll
                for (int mf = 0; mf < 4; mf++)
#pragma unroll
                    for (int nt = 0; nt < 2; nt++)
                        mma16816(acc[mf][nf2 * 2 + nt], ah[mf], &bh[nt * 2]);
            }
        }
        if (++stg == STAGES) { stg = 0; ph ^= 1; }
    }

    // ---- epilogue: acc * 2^-18 + bias -> y, float2 stores ----
    const int row0 = bm * BM + wm * 64 + (lane >> 2);
    const int col0 = bn * BN + wn * 64 + (lane & 3) * 2;
#pragma unroll
    for (int mf = 0; mf < 4; mf++) {
#pragma unroll
        for (int n8 = 0; n8 < 8; n8++) {
            int col = col0 + n8 * 8;
            float b0 = bias[col], b1 = bias[col + 1];
            float* p0 = y + (size_t)(row0 + mf * 16) * OUT_F + col;
            float* p1 = y + (size_t)(row0 + mf * 16 + 8) * OUT_F + col;
            float2 v0 = make_float2(fmaf(acc[mf][n8][0], H_INVSCALE, b0),
                                    fmaf(acc[mf][n8][1], H_INVSCALE, b1));
            float2 v1 = make_float2(fmaf(acc[mf][n8][2], H_INVSCALE, b0),
                                    fmaf(acc[mf][n8][3], H_INVSCALE, b1));
            *reinterpret_cast<float2*>(p0) = v0;
            *reinterpret_cast<float2*>(p1) = v1;
        }
    }
}

// ===================== Launch =====================
extern "C" void kernel_launch(void* const* d_in, const int* in_sizes, int n_in,
                              void* d_out, int out_size) {
    const float* x    = (const float*)d_in[0];   // (8192, 2048)
    const float* rule = (const float*)d_in[1];   // (4, 4, 4)
    const float* W    = (const float*)d_in[2];   // (4, 512, 2048)
    const float* b    = (const float*)d_in[3];   // (8192,)
    float* y          = (float*)d_out;           // (8192, 8192)

    cudaFuncSetAttribute(build_h_kernel, cudaFuncAttributeMaxDynamicSharedMemorySize,
                         4 * 64 * 65 * 4);
    cudaFuncSetAttribute(phm_gemm_kernel, cudaFuncAttributeMaxDynamicSharedMemorySize,
                         SM_HDR + STAGES * STG_SZ);

    // 1) x -> fp16 (pre-swizzled tiles, 8 floats/thread)
    split_x_kernel<<<8192, 256>>>(x);
    // 2) H^T (K-major), scaled by 2^18, fp16 (pre-swizzled tiles)
    build_h_kernel<<<dim3(2048 / 64, 512 / 64), 256, 4 * 64 * 65 * 4>>>(rule, W);
    // 3) GEMM: y = x @ H + b, bulk-copy pipeline, 2 CTAs/SM
    phm_gemm_kernel<<<dim3(OUT_F / BN, TOKENS / BM), NTHREADS,
                      SM_HDR + STAGES * STG_SZ>>>(y, b);
}

// round 10
// speedup vs baseline: 1.3448x; 1.0860x over previous
#include <cuda_runtime.h>
#include <cuda_bf16.h>
#include <cuda_fp16.h>
#include <cstdint>

// ===================== Problem constants =====================
#define TOKENS   8192
#define IN_F     2048
#define OUT_F    8192
#define BM 128
#define BN 128
#define BK 64                  // fp16 elems per K-chunk
#define NCHUNK (IN_F / BK)     // 32
#define STAGES 3
// Tiled global layout, PRE-SWIZZLED: tile (b, kc) = 128 rows x 64 halfs (128B pitch).
// Within each 128B row, 16B chunk c lives at position c ^ (row & 7).
#define TILE_H  (128 * 64)     // halfs per tile (8192)
#define TILE_B  (128 * 128)    // bytes per tile (16384)
#define STG_SZ  (2 * TILE_B)   // A tile + B tile per stage (32768)
#define SA_OFF  0
#define SB_OFF  TILE_B
#define SM_HDR  128            // mbarriers live in [0, 128)
#define NTHREADS 128           // 4 warps, warp grid 2x2, warp tile 64x64

// H is ~2e-6 (fp16 subnormal range) -> scale by 2^18, undo in epilogue.
#define H_SCALE   262144.0f
#define H_INVSCALE 3.814697265625e-06f

// ===================== Device scratch (no allocs allowed) =====================
// Tile-major: [b][kc][row][swizzled 16B chunks]
__device__ __align__(256) __half g_A[(size_t)(TOKENS / 128) * NCHUNK * TILE_H];
__device__ __align__(256) __half g_B[(size_t)(OUT_F / 128) * NCHUNK * TILE_H];

// ===================== Helpers (base-target PTX: sm_80/sm_90 era) =====================
__device__ __forceinline__ uint32_t smem_u32(const void* p) {
    uint32_t a;
    asm("{ .reg .u64 t; cvta.to.shared.u64 t, %1; cvt.u32.u64 %0, t; }" : "=r"(a) : "l"(p));
    return a;
}
__device__ __forceinline__ void ldsm_x4(uint32_t* r, uint32_t addr) {
    asm volatile("ldmatrix.sync.aligned.m8n8.x4.shared.b16 {%0,%1,%2,%3}, [%4];"
                 : "=r"(r[0]), "=r"(r[1]), "=r"(r[2]), "=r"(r[3]) : "r"(addr));
}
__device__ __forceinline__ void mma16816(float* c, const uint32_t* a, const uint32_t* b) {
    asm volatile(
        "mma.sync.aligned.m16n8k16.row.col.f32.f16.f16.f32 "
        "{%0,%1,%2,%3}, {%4,%5,%6,%7}, {%8,%9}, {%0,%1,%2,%3};"
        : "+f"(c[0]), "+f"(c[1]), "+f"(c[2]), "+f"(c[3])
        : "r"(a[0]), "r"(a[1]), "r"(a[2]), "r"(a[3]), "r"(b[0]), "r"(b[1]));
}
// Bulk async copy global->shared with mbarrier transaction accounting (sm_90 base)
__device__ __forceinline__ void bulk_cp(uint32_t dst, const void* src, uint32_t bytes,
                                        uint32_t mbar) {
    asm volatile(
        "cp.async.bulk.shared::cluster.global.mbarrier::complete_tx::bytes [%0], [%1], %2, [%3];"
        :: "r"(dst), "l"(src), "r"(bytes), "r"(mbar) : "memory");
}
#define MBAR_INIT(m, cnt) \
    asm volatile("mbarrier.init.shared.b64 [%0], %1;" :: "r"((uint32_t)(m)), "r"((uint32_t)(cnt)) : "memory")
#define MBAR_EXPECT_TX(m, bytes) \
    asm volatile("mbarrier.arrive.expect_tx.shared.b64 _, [%0], %1;" \
                 :: "r"((uint32_t)(m)), "r"((uint32_t)(bytes)) : "memory")
#define MBAR_ARRIVE(m) \
    asm volatile("mbarrier.arrive.shared.b64 _, [%0];" :: "r"((uint32_t)(m)) : "memory")
#define MBAR_WAIT_PARITY(mbar, parity) do {                                               \
    uint32_t _m = (uint32_t)(mbar);                                                       \
    uint32_t _p = (uint32_t)(parity);                                                     \
    uint32_t _done;                                                                       \
    asm volatile("{\n\t.reg .pred p;\n\t"                                                 \
        "mbarrier.try_wait.parity.acquire.cta.shared::cta.b64 p, [%1], %2;\n\t"           \
        "selp.b32 %0, 1, 0, p;\n\t}"                                                      \
        : "=r"(_done) : "r"(_m), "r"(_p) : "memory");                                     \
    if (!_done) {                                                                         \
        asm volatile("{\n\t.reg .pred P1;\n\t"                                            \
            "WL_%=:\n\t"                                                                  \
            "mbarrier.try_wait.parity.acquire.cta.shared::cta.b64 P1, [%0], %1, 0x989680;\n\t" \
            "@P1 bra.uni WD_%=;\n\t"                                                      \
            "bra.uni WL_%=;\n\t"                                                          \
            "WD_%=:\n\t}"                                                                 \
            :: "r"(_m), "r"(_p) : "memory");                                              \
    }                                                                                     \
} while (0)

// ===================== Kernel 1: x -> fp16, pre-swizzled tiled layout =====================
// One thread = 8 consecutive floats = one 16B fp16 chunk at its swizzled slot.
__global__ void split_x_kernel(const float* __restrict__ x) {
    size_t j = (size_t)blockIdx.x * blockDim.x + threadIdx.x;  // 8-float group index
    const float4* xp = reinterpret_cast<const float4*>(x) + 2 * j;
    float4 v0 = xp[0], v1 = xp[1];
    int m  = (int)(j >> 8);             // 256 groups per row (2048/8)
    int k  = ((int)j & 255) * 8;
    int bm = m >> 7, row = m & 127;
    int kc = k >> 6, col = k & 63;      // col multiple of 8
    int swc = (col >> 3) ^ (row & 7);
    size_t off = ((size_t)(bm * NCHUNK + kc) * 128 + row) * 64 + swc * 8;
    union { uint4 u; __half2 h[4]; } pk;
    pk.h[0] = __halves2half2(__float2half_rn(v0.x), __float2half_rn(v0.y));
    pk.h[1] = __halves2half2(__float2half_rn(v0.z), __float2half_rn(v0.w));
    pk.h[2] = __halves2half2(__float2half_rn(v1.x), __float2half_rn(v1.y));
    pk.h[3] = __halves2half2(__float2half_rn(v1.z), __float2half_rn(v1.w));
    *reinterpret_cast<uint4*>(g_A + off) = pk.u;
}

// ===================== Kernel 2: build H^T (K-major), scaled fp16, swizzled tiles =====================
// Ht[n, k] = sum_i rule[i, a, kq] * W[i, c, p],  k = a*512 + c, n = kq*2048 + p.
// Each thread builds one 16B chunk (8 consecutive k) in registers -> uint4 store.
__global__ void build_h_kernel(const float* __restrict__ rule, const float* __restrict__ W) {
    extern __shared__ float Ws[];  // [4][64][65] padded
    __shared__ float rs[64];
    const int t = threadIdx.x;          // 256 threads
    const int p0 = blockIdx.x * 64;     // out_per dim (2048)
    const int c0 = blockIdx.y * 64;     // in_per dim (512)

    for (int idx = t; idx < 4 * 64 * 64; idx += 256) {
        int i = idx >> 12;
        int cc = (idx >> 6) & 63;
        int pp = idx & 63;
        Ws[(i * 64 + cc) * 65 + pp] =
            W[(size_t)i * 512 * 2048 + (size_t)(c0 + cc) * 2048 + (p0 + pp)];
    }
    if (t < 64) rs[t] = rule[t];
    __syncthreads();

#pragma unroll
    for (int it = 0; it < 2; it++) {
        int item = it * 256 + t;        // 0..511
        int ch = item & 7;              // 16B chunk within the 64-wide k slice
        int pp = item >> 3;             // 0..63
#pragma unroll
        for (int a = 0; a < 4; a++) {
#pragma unroll
            for (int kq = 0; kq < 4; kq++) {
                float r0 = rs[0 * 16 + a * 4 + kq];
                float r1 = rs[1 * 16 + a * 4 + kq];
                float r2 = rs[2 * 16 + a * 4 + kq];
                float r3 = rs[3 * 16 + a * 4 + kq];
                union { uint4 u; __half h[8]; } out;
#pragma unroll
                for (int e = 0; e < 8; e++) {
                    int cc = ch * 8 + e;
                    float v = r0 * Ws[(0 * 64 + cc) * 65 + pp]
                            + r1 * Ws[(1 * 64 + cc) * 65 + pp]
                            + r2 * Ws[(2 * 64 + cc) * 65 + pp]
                            + r3 * Ws[(3 * 64 + cc) * 65 + pp];
                    out.h[e] = __float2half_rn(v * H_SCALE);
                }
                int n = kq * 2048 + p0 + pp;
                int row = n & 127, bn = n >> 7;
                int kc = a * 8 + blockIdx.y;       // (a*512 + c0 + ch*8) >> 6
                int swc = ch ^ (row & 7);
                size_t off = ((size_t)(bn * NCHUNK + kc) * 128 + row) * 64 + swc * 8;
                *reinterpret_cast<uint4*>(g_B + off) = out.u;
            }
        }
    }
}

// ===================== Kernel 3: fp16 mma.sync GEMM, bulk-copy pipeline, 2 CTAs/SM =====================
// 128x128 CTA tile, 4 warps (64x64 warp tiles), 3-stage pipeline fed by ONE
// 16KB cp.async.bulk per tile per chunk. Full/empty mbarrier handshake instead
// of per-chunk __syncthreads: consumers arrive empty[slot] (count 4) after
// compute; producer waits empty before refilling that slot.
__global__ void __launch_bounds__(NTHREADS, 2)
phm_gemm_kernel(float* __restrict__ y, const float* __restrict__ bias) {
    extern __shared__ char smem[];
    const uint32_t sb = smem_u32(smem);
    const int tid = threadIdx.x;
    const int wid = tid >> 5, lane = tid & 31;
    const int wm = wid >> 1, wn = wid & 1;     // 2 x 2 warp grid
    const int bn = blockIdx.x, bm = blockIdx.y;

    const __half* At = g_A + (size_t)bm * NCHUNK * TILE_H;
    const __half* Bt = g_B + (size_t)bn * NCHUNK * TILE_H;

    // full[s] at sb + s*8 (count 1, tx); empty[s] at sb + 24 + s*8 (count 4)
    if (tid == 0) {
        MBAR_INIT(sb + 0, 1);
        MBAR_INIT(sb + 8, 1);
        MBAR_INIT(sb + 16, 1);
        MBAR_INIT(sb + 24, 4);
        MBAR_INIT(sb + 32, 4);
        MBAR_INIT(sb + 40, 4);
    }
    __syncthreads();

    // prologue: fill stages 0..STAGES-2
    if (tid == 0) {
#pragma unroll
        for (int p = 0; p < STAGES - 1; p++) {
            uint32_t mb = sb + p * 8;
            uint32_t s = sb + SM_HDR + p * STG_SZ;
            MBAR_EXPECT_TX(mb, STG_SZ);
            bulk_cp(s + SA_OFF, At + (size_t)p * TILE_H, TILE_B, mb);
            bulk_cp(s + SB_OFF, Bt + (size_t)p * TILE_H, TILE_B, mb);
        }
    }

    float acc[4][8][4];                          // warp tile 64x64
#pragma unroll
    for (int mf = 0; mf < 4; mf++)
#pragma unroll
        for (int n8 = 0; n8 < 8; n8++)
#pragma unroll
            for (int q = 0; q < 4; q++) acc[mf][n8][q] = 0.0f;

    // lane addressing for ldmatrix
    const int a_row = wm * 64 + (lane & 15);
    const int a_cpick = lane >> 4;                 // 0/1 -> k +0 / +8
    const int bg = lane >> 3;                      // 0..3
    const int b_row = wn * 64 + ((bg >> 1) << 3) + (lane & 7);
    const int b_cpick = bg & 1;

    int stg = 0, ph = 0;
    int ecyc = 0, epar = 0;                        // producer empty-parity cursor
    for (int kc = 0; kc < NCHUNK; kc++) {
        MBAR_WAIT_PARITY(sb + stg * 8, ph);        // chunk kc data ready

        // producer: refill slot (kc+2)%3 with chunk kc+2 once consumers drained kc-1
        if (tid == 0 && kc + STAGES - 1 < NCHUNK) {
            int ns = stg + STAGES - 1; if (ns >= STAGES) ns -= STAGES;
            if (kc >= 1) {                          // slot held chunk kc-1 before
                MBAR_WAIT_PARITY(sb + 24 + ns * 8, epar);
                if (++ecyc == STAGES) { ecyc = 0; epar ^= 1; }
            }
            uint32_t mb = sb + ns * 8;
            uint32_t d = sb + SM_HDR + ns * STG_SZ;
            MBAR_EXPECT_TX(mb, STG_SZ);
            bulk_cp(d + SA_OFF, At + (size_t)(kc + STAGES - 1) * TILE_H, TILE_B, mb);
            bulk_cp(d + SB_OFF, Bt + (size_t)(kc + STAGES - 1) * TILE_H, TILE_B, mb);
        }

        const uint32_t s = sb + SM_HDR + stg * STG_SZ;
#pragma unroll
        for (int ks = 0; ks < 4; ks++) {          // 4 x k16 per 64-wide chunk
            uint32_t ah[4][4];
#pragma unroll
            for (int mf = 0; mf < 4; mf++) {
                int row = a_row + mf * 16;
                int cidx = ks * 2 + a_cpick;
                uint32_t ad = s + SA_OFF + (uint32_t)(row * 128 + ((cidx ^ (row & 7)) * 16));
                ldsm_x4(ah[mf], ad);
            }
#pragma unroll
            for (int nf2 = 0; nf2 < 4; nf2++) {
                int n = b_row + nf2 * 16;
                int cidx = ks * 2 + b_cpick;
                uint32_t bd = s + SB_OFF + (uint32_t)(n * 128 + ((cidx ^ (n & 7)) * 16));
                uint32_t bh[4];
                ldsm_x4(bh, bd);
#pragma unroll
                for (int mf = 0; mf < 4; mf++)
#pragma unroll
                    for (int nt = 0; nt < 2; nt++)
                        mma16816(acc[mf][nf2 * 2 + nt], ah[mf], &bh[nt * 2]);
            }
        }

        if (lane == 0) MBAR_ARRIVE(sb + 24 + stg * 8);  // this warp done with slot
        if (++stg == STAGES) { stg = 0; ph ^= 1; }
    }

    // ---- epilogue: acc * 2^-18 + bias -> y, float2 stores ----
    const int row0 = bm * BM + wm * 64 + (lane >> 2);
    const int col0 = bn * BN + wn * 64 + (lane & 3) * 2;
#pragma unroll
    for (int mf = 0; mf < 4; mf++) {
#pragma unroll
        for (int n8 = 0; n8 < 8; n8++) {
            int col = col0 + n8 * 8;
            float b0 = bias[col], b1 = bias[col + 1];
            float* p0 = y + (size_t)(row0 + mf * 16) * OUT_F + col;
            float* p1 = y + (size_t)(row0 + mf * 16 + 8) * OUT_F + col;
            float2 v0 = make_float2(fmaf(acc[mf][n8][0], H_INVSCALE, b0),
                                    fmaf(acc[mf][n8][1], H_INVSCALE, b1));
            float2 v1 = make_float2(fmaf(acc[mf][n8][2], H_INVSCALE, b0),
                                    fmaf(acc[mf][n8][3], H_INVSCALE, b1));
            *reinterpret_cast<float2*>(p0) = v0;
            *reinterpret_cast<float2*>(p1) = v1;
        }
    }
}

// ===================== Launch =====================
extern "C" void kernel_launch(void* const* d_in, const int* in_sizes, int n_in,
                              void* d_out, int out_size) {
    const float* x    = (const float*)d_in[0];   // (8192, 2048)
    const float* rule = (const float*)d_in[1];   // (4, 4, 4)
    const float* W    = (const float*)d_in[2];   // (4, 512, 2048)
    const float* b    = (const float*)d_in[3];   // (8192,)
    float* y          = (float*)d_out;           // (8192, 8192)

    cudaFuncSetAttribute(build_h_kernel, cudaFuncAttributeMaxDynamicSharedMemorySize,
                         4 * 64 * 65 * 4);
    cudaFuncSetAttribute(phm_gemm_kernel, cudaFuncAttributeMaxDynamicSharedMemorySize,
                         SM_HDR + STAGES * STG_SZ);

    // 1) x -> fp16 (pre-swizzled tiles, 8 floats/thread)
    split_x_kernel<<<8192, 256>>>(x);
    // 2) H^T (K-major), scaled by 2^18, fp16 (pre-swizzled tiles, uint4 stores)
    build_h_kernel<<<dim3(2048 / 64, 512 / 64), 256, 4 * 64 * 65 * 4>>>(rule, W);
    // 3) GEMM: y = x @ H + b, bulk-copy pipeline, full/empty handshake, 2 CTAs/SM
    phm_gemm_kernel<<<dim3(OUT_F / BN, TOKENS / BM), NTHREADS,
                      SM_HDR + STAGES * STG_SZ>>>(y, b);
}

// round 11
// speedup vs baseline: 1.3457x; 1.0007x over previous
#include <cuda_runtime.h>
#include <cuda_bf16.h>
#include <cuda_fp16.h>
#include <cstdint>

// ===================== Problem constants =====================
#define TOKENS   8192
#define IN_F     2048
#define OUT_F    8192
#define BM 128
#define BN 128
#define BK 64                  // fp16 elems per K-chunk
#define NCHUNK (IN_F / BK)     // 32
#define STAGES 3
// Tiled global layout, PRE-SWIZZLED: tile (b, kc) = 128 rows x 64 halfs (128B pitch).
// Within each 128B row, 16B chunk c lives at position c ^ (row & 7).
#define TILE_H  (128 * 64)     // halfs per tile (8192)
#define TILE_B  (128 * 128)    // bytes per tile (16384)
#define STG_SZ  (2 * TILE_B)   // A tile + B tile per stage (32768)
#define SA_OFF  0
#define SB_OFF  TILE_B
#define SM_HDR  128            // mbarriers live in [0, 128)
#define NTHREADS 128           // 4 warps, warp grid 2x2, warp tile 64x64

// H is ~2e-6 (fp16 subnormal range) -> scale by 2^18, undo in epilogue.
#define H_SCALE   262144.0f
#define H_INVSCALE 3.814697265625e-06f

#define NBLK_H 256             // build_h blocks (32 x 8)
#define NBLK_X 8192            // split_x blocks

// ===================== Device scratch (no allocs allowed) =====================
// Tile-major: [b][kc][row][swizzled 16B chunks]
__device__ __align__(256) __half g_A[(size_t)(TOKENS / 128) * NCHUNK * TILE_H];
__device__ __align__(256) __half g_B[(size_t)(OUT_F / 128) * NCHUNK * TILE_H];

// ===================== Helpers (base-target PTX: sm_80/sm_90 era) =====================
__device__ __forceinline__ uint32_t smem_u32(const void* p) {
    uint32_t a;
    asm("{ .reg .u64 t; cvta.to.shared.u64 t, %1; cvt.u32.u64 %0, t; }" : "=r"(a) : "l"(p));
    return a;
}
__device__ __forceinline__ void ldsm_x4(uint32_t* r, uint32_t addr) {
    asm volatile("ldmatrix.sync.aligned.m8n8.x4.shared.b16 {%0,%1,%2,%3}, [%4];"
                 : "=r"(r[0]), "=r"(r[1]), "=r"(r[2]), "=r"(r[3]) : "r"(addr));
}
__device__ __forceinline__ void mma16816(float* c, const uint32_t* a, const uint32_t* b) {
    asm volatile(
        "mma.sync.aligned.m16n8k16.row.col.f32.f16.f16.f32 "
        "{%0,%1,%2,%3}, {%4,%5,%6,%7}, {%8,%9}, {%0,%1,%2,%3};"
        : "+f"(c[0]), "+f"(c[1]), "+f"(c[2]), "+f"(c[3])
        : "r"(a[0]), "r"(a[1]), "r"(a[2]), "r"(a[3]), "r"(b[0]), "r"(b[1]));
}
// Bulk async copy global->shared with mbarrier transaction accounting (sm_90 base)
__device__ __forceinline__ void bulk_cp(uint32_t dst, const void* src, uint32_t bytes,
                                        uint32_t mbar) {
    asm volatile(
        "cp.async.bulk.shared::cluster.global.mbarrier::complete_tx::bytes [%0], [%1], %2, [%3];"
        :: "r"(dst), "l"(src), "r"(bytes), "r"(mbar) : "memory");
}
__device__ __forceinline__ void st_cs_f2(float* p, float2 v) {
    asm volatile("st.global.cs.v2.f32 [%0], {%1, %2};" :: "l"(p), "f"(v.x), "f"(v.y) : "memory");
}
#define MBAR_INIT(m, cnt) \
    asm volatile("mbarrier.init.shared.b64 [%0], %1;" :: "r"((uint32_t)(m)), "r"((uint32_t)(cnt)) : "memory")
#define MBAR_EXPECT_TX(m, bytes) \
    asm volatile("mbarrier.arrive.expect_tx.shared.b64 _, [%0], %1;" \
                 :: "r"((uint32_t)(m)), "r"((uint32_t)(bytes)) : "memory")
#define MBAR_ARRIVE(m) \
    asm volatile("mbarrier.arrive.shared.b64 _, [%0];" :: "r"((uint32_t)(m)) : "memory")
#define MBAR_WAIT_PARITY(mbar, parity) do {                                               \
    uint32_t _m = (uint32_t)(mbar);                                                       \
    uint32_t _p = (uint32_t)(parity);                                                     \
    uint32_t _done;                                                                       \
    asm volatile("{\n\t.reg .pred p;\n\t"                                                 \
        "mbarrier.try_wait.parity.acquire.cta.shared::cta.b64 p, [%1], %2;\n\t"           \
        "selp.b32 %0, 1, 0, p;\n\t}"                                                      \
        : "=r"(_done) : "r"(_m), "r"(_p) : "memory");                                     \
    if (!_done) {                                                                         \
        asm volatile("{\n\t.reg .pred P1;\n\t"                                            \
            "WL_%=:\n\t"                                                                  \
            "mbarrier.try_wait.parity.acquire.cta.shared::cta.b64 P1, [%0], %1, 0x989680;\n\t" \
            "@P1 bra.uni WD_%=;\n\t"                                                      \
            "bra.uni WL_%=;\n\t"                                                          \
            "WD_%=:\n\t}"                                                                 \
            :: "r"(_m), "r"(_p) : "memory");                                              \
    }                                                                                     \
} while (0)

// ===================== Fused prologue: build_h (blocks 0..255) + split_x (rest) =====
// h-blocks FIRST so the compute-bound H build runs concurrently with the
// DRAM-bound x conversion streaming through the remaining SMs.
__global__ void prologue_kernel(const float* __restrict__ x,
                                const float* __restrict__ rule,
                                const float* __restrict__ W) {
    const int t = threadIdx.x;  // 256 threads
    if (blockIdx.x >= NBLK_H) {
        // ---------------- split_x: one thread = 8 floats -> one swizzled 16B chunk
        size_t j = (size_t)(blockIdx.x - NBLK_H) * blockDim.x + t;
        const float4* xp = reinterpret_cast<const float4*>(x) + 2 * j;
        float4 v0 = xp[0], v1 = xp[1];
        int m  = (int)(j >> 8);             // 256 groups per row (2048/8)
        int k  = ((int)j & 255) * 8;
        int bm = m >> 7, row = m & 127;
        int kc = k >> 6, col = k & 63;
        int swc = (col >> 3) ^ (row & 7);
        size_t off = ((size_t)(bm * NCHUNK + kc) * 128 + row) * 64 + swc * 8;
        union { uint4 u; __half2 h[4]; } pk;
        pk.h[0] = __halves2half2(__float2half_rn(v0.x), __float2half_rn(v0.y));
        pk.h[1] = __halves2half2(__float2half_rn(v0.z), __float2half_rn(v0.w));
        pk.h[2] = __halves2half2(__float2half_rn(v1.x), __float2half_rn(v1.y));
        pk.h[3] = __halves2half2(__float2half_rn(v1.z), __float2half_rn(v1.w));
        *reinterpret_cast<uint4*>(g_A + off) = pk.u;
        return;
    }

    // ---------------- build_h: Ht[n,k] = sum_i rule[i,a,kq] * W[i,c,p]
    extern __shared__ float Ws[];  // [4][64][65] padded
    __shared__ float rs[64];
    const int hb = blockIdx.x;
    const int p0 = (hb & 31) * 64;      // out_per dim (2048/64 = 32)
    const int c0 = (hb >> 5) * 64;      // in_per dim (512/64 = 8)

    for (int idx = t; idx < 4 * 64 * 64; idx += 256) {
        int i = idx >> 12;
        int cc = (idx >> 6) & 63;
        int pp = idx & 63;
        Ws[(i * 64 + cc) * 65 + pp] =
            W[(size_t)i * 512 * 2048 + (size_t)(c0 + cc) * 2048 + (p0 + pp)];
    }
    if (t < 64) rs[t] = rule[t];
    __syncthreads();

#pragma unroll
    for (int it = 0; it < 2; it++) {
        int item = it * 256 + t;        // 0..511
        int ch = item & 7;              // 16B chunk within the 64-wide k slice
        int pp = item >> 3;             // 0..63
#pragma unroll
        for (int a = 0; a < 4; a++) {
#pragma unroll
            for (int kq = 0; kq < 4; kq++) {
                float r0 = rs[0 * 16 + a * 4 + kq];
                float r1 = rs[1 * 16 + a * 4 + kq];
                float r2 = rs[2 * 16 + a * 4 + kq];
                float r3 = rs[3 * 16 + a * 4 + kq];
                union { uint4 u; __half h[8]; } out;
#pragma unroll
                for (int e = 0; e < 8; e++) {
                    int cc = ch * 8 + e;
                    float v = r0 * Ws[(0 * 64 + cc) * 65 + pp]
                            + r1 * Ws[(1 * 64 + cc) * 65 + pp]
                            + r2 * Ws[(2 * 64 + cc) * 65 + pp]
                            + r3 * Ws[(3 * 64 + cc) * 65 + pp];
                    out.h[e] = __float2half_rn(v * H_SCALE);
                }
                int n = kq * 2048 + p0 + pp;
                int row = n & 127, bn = n >> 7;
                int kc = a * 8 + (hb >> 5);        // (a*512 + c0 + ch*8) >> 6
                int swc = ch ^ (row & 7);
                size_t off = ((size_t)(bn * NCHUNK + kc) * 128 + row) * 64 + swc * 8;
                *reinterpret_cast<uint4*>(g_B + off) = out.u;
            }
        }
    }
}

// ===================== GEMM: fp16 mma.sync, bulk-copy pipeline, 2 CTAs/SM =====================
// 128x128 CTA tile, 4 warps (64x64 warp tiles), 3-stage pipeline fed by ONE
// 16KB cp.async.bulk per tile per chunk. Full/empty mbarrier handshake.
__global__ void __launch_bounds__(NTHREADS, 2)
phm_gemm_kernel(float* __restrict__ y, const float* __restrict__ bias) {
    extern __shared__ char smem[];
    const uint32_t sb = smem_u32(smem);
    const int tid = threadIdx.x;
    const int wid = tid >> 5, lane = tid & 31;
    const int wm = wid >> 1, wn = wid & 1;     // 2 x 2 warp grid
    const int bn = blockIdx.x, bm = blockIdx.y;

    const __half* At = g_A + (size_t)bm * NCHUNK * TILE_H;
    const __half* Bt = g_B + (size_t)bn * NCHUNK * TILE_H;

    // full[s] at sb + s*8 (count 1, tx); empty[s] at sb + 24 + s*8 (count 4)
    if (tid == 0) {
        MBAR_INIT(sb + 0, 1);
        MBAR_INIT(sb + 8, 1);
        MBAR_INIT(sb + 16, 1);
        MBAR_INIT(sb + 24, 4);
        MBAR_INIT(sb + 32, 4);
        MBAR_INIT(sb + 40, 4);
    }
    __syncthreads();

    // prologue: fill stages 0..STAGES-2
    if (tid == 0) {
#pragma unroll
        for (int p = 0; p < STAGES - 1; p++) {
            uint32_t mb = sb + p * 8;
            uint32_t s = sb + SM_HDR + p * STG_SZ;
            MBAR_EXPECT_TX(mb, STG_SZ);
            bulk_cp(s + SA_OFF, At + (size_t)p * TILE_H, TILE_B, mb);
            bulk_cp(s + SB_OFF, Bt + (size_t)p * TILE_H, TILE_B, mb);
        }
    }

    float acc[4][8][4];                          // warp tile 64x64
#pragma unroll
    for (int mf = 0; mf < 4; mf++)
#pragma unroll
        for (int n8 = 0; n8 < 8; n8++)
#pragma unroll
            for (int q = 0; q < 4; q++) acc[mf][n8][q] = 0.0f;

    // lane addressing for ldmatrix
    const int a_row = wm * 64 + (lane & 15);
    const int a_cpick = lane >> 4;                 // 0/1 -> k +0 / +8
    const int bg = lane >> 3;                      // 0..3
    const int b_row = wn * 64 + ((bg >> 1) << 3) + (lane & 7);
    const int b_cpick = bg & 1;

    int stg = 0, ph = 0;
    int ecyc = 0, epar = 0;                        // producer empty-parity cursor
    for (int kc = 0; kc < NCHUNK; kc++) {
        MBAR_WAIT_PARITY(sb + stg * 8, ph);        // chunk kc data ready

        // producer: refill slot (kc+2)%3 once consumers drained chunk kc-1
        if (tid == 0 && kc + STAGES - 1 < NCHUNK) {
            int ns = stg + STAGES - 1; if (ns >= STAGES) ns -= STAGES;
            if (kc >= 1) {
                MBAR_WAIT_PARITY(sb + 24 + ns * 8, epar);
                if (++ecyc == STAGES) { ecyc = 0; epar ^= 1; }
            }
            uint32_t mb = sb + ns * 8;
            uint32_t d = sb + SM_HDR + ns * STG_SZ;
            MBAR_EXPECT_TX(mb, STG_SZ);
            bulk_cp(d + SA_OFF, At + (size_t)(kc + STAGES - 1) * TILE_H, TILE_B, mb);
            bulk_cp(d + SB_OFF, Bt + (size_t)(kc + STAGES - 1) * TILE_H, TILE_B, mb);
        }

        const uint32_t s = sb + SM_HDR + stg * STG_SZ;
#pragma unroll
        for (int ks = 0; ks < 4; ks++) {          // 4 x k16 per 64-wide chunk
            uint32_t ah[4][4];
#pragma unroll
            for (int mf = 0; mf < 4; mf++) {
                int row = a_row + mf * 16;
                int cidx = ks * 2 + a_cpick;
                uint32_t ad = s + SA_OFF + (uint32_t)(row * 128 + ((cidx ^ (row & 7)) * 16));
                ldsm_x4(ah[mf], ad);
            }
#pragma unroll
            for (int nf2 = 0; nf2 < 4; nf2++) {
                int n = b_row + nf2 * 16;
                int cidx = ks * 2 + b_cpick;
                uint32_t bd = s + SB_OFF + (uint32_t)(n * 128 + ((cidx ^ (n & 7)) * 16));
                uint32_t bh[4];
                ldsm_x4(bh, bd);
#pragma unroll
                for (int mf = 0; mf < 4; mf++)
#pragma unroll
                    for (int nt = 0; nt < 2; nt++)
                        mma16816(acc[mf][nf2 * 2 + nt], ah[mf], &bh[nt * 2]);
            }
        }

        if (lane == 0) MBAR_ARRIVE(sb + 24 + stg * 8);  // this warp done with slot
        if (++stg == STAGES) { stg = 0; ph ^= 1; }
    }

    // ---- epilogue: acc * 2^-18 + bias -> y, streaming float2 stores ----
    const int row0 = bm * BM + wm * 64 + (lane >> 2);
    const int col0 = bn * BN + wn * 64 + (lane & 3) * 2;
#pragma unroll
    for (int mf = 0; mf < 4; mf++) {
#pragma unroll
        for (int n8 = 0; n8 < 8; n8++) {
            int col = col0 + n8 * 8;
            float b0 = bias[col], b1 = bias[col + 1];
            float* p0 = y + (size_t)(row0 + mf * 16) * OUT_F + col;
            float* p1 = y + (size_t)(row0 + mf * 16 + 8) * OUT_F + col;
            st_cs_f2(p0, make_float2(fmaf(acc[mf][n8][0], H_INVSCALE, b0),
                                     fmaf(acc[mf][n8][1], H_INVSCALE, b1)));
            st_cs_f2(p1, make_float2(fmaf(acc[mf][n8][2], H_INVSCALE, b0),
                                     fmaf(acc[mf][n8][3], H_INVSCALE, b1)));
        }
    }
}

// ===================== Launch =====================
extern "C" void kernel_launch(void* const* d_in, const int* in_sizes, int n_in,
                              void* d_out, int out_size) {
    const float* x    = (const float*)d_in[0];   // (8192, 2048)
    const float* rule = (const float*)d_in[1];   // (4, 4, 4)
    const float* W    = (const float*)d_in[2];   // (4, 512, 2048)
    const float* b    = (const float*)d_in[3];   // (8192,)
    float* y          = (float*)d_out;           // (8192, 8192)

    cudaFuncSetAttribute(prologue_kernel, cudaFuncAttributeMaxDynamicSharedMemorySize,
                         4 * 64 * 65 * 4);
    cudaFuncSetAttribute(phm_gemm_kernel, cudaFuncAttributeMaxDynamicSharedMemorySize,
                         SM_HDR + STAGES * STG_SZ);

    // 1) fused prologue: build_h (256 blocks, first) + split_x (8192 blocks)
    prologue_kernel<<<NBLK_H + NBLK_X, 256, 4 * 64 * 65 * 4>>>(x, rule, W);
    // 2) GEMM: y = x @ H + b, bulk-copy pipeline, full/empty handshake, 2 CTAs/SM
    phm_gemm_kernel<<<dim3(OUT_F / BN, TOKENS / BM), NTHREADS,
                      SM_HDR + STAGES * STG_SZ>>>(y, b);
}